// round 12
// baseline (speedup 1.0000x reference)
#include <cuda_runtime.h>
#include <cuda_fp16.h>
#include <stdint.h>

#define BB 16
#define PP 8192
#define MM 128
#define KNN 16
#define DD 768
#define QQ (BB*MM)      // 2048 queries/tokens
#define RR (QQ*KNN)     // 32768 gathered rows

// ---------------- scratch (device globals; no allocation allowed) ----------------
__device__ float  g_cent[QQ*4];
__device__ int    g_knn[RR];
__device__ __half g_bufA[(size_t)RR*768];
__device__ __half g_bufB[(size_t)RR*768];
__device__ __half g_pool[(size_t)QQ*DD];
__device__ __half g_h[(size_t)QQ*DD];
// transposed weights [N][K] (K-major so B operand is k-contiguous = "col" for mma)
#define OFF_W2T  0
#define OFF_W3T  (512*256)
#define OFF_W4T  (OFF_W3T + 768*512)
#define OFF_WA1T (OFF_W4T + 768*768)
#define OFF_WA2T (OFF_WA1T + 768*768)
__device__ __half g_wt[OFF_WA2T + 768*768];

// ---------------- FPS: one block per batch, points register-resident -------------
__global__ __launch_bounds__(1024) void fps_kernel(const float* __restrict__ coords,
                                                   float* __restrict__ cent_out2)
{
    int b = blockIdx.x;
    int tid = threadIdx.x;
    float px[8], py[8], pz[8], pw[8], dmin[8];
#pragma unroll
    for (int i = 0; i < 8; i++) {
        int p = tid + i * 1024;
        const float* c = coords + ((size_t)b * PP + p) * 5;
        px[i] = c[1]; py[i] = c[2]; pz[i] = c[3]; pw[i] = c[4];
        dmin[i] = 1e30f;
    }
    __shared__ float last[4];
    __shared__ unsigned long long red[32];
    __shared__ int cur_s;
    int cur = 0;
    for (int m = 0; m < MM; m++) {
        if (tid == (cur & 1023)) {
            int i = cur >> 10;
            last[0] = px[i]; last[1] = py[i]; last[2] = pz[i]; last[3] = pw[i];
            float* o  = g_cent + ((size_t)b * MM + m) * 4;
            o[0] = px[i]; o[1] = py[i]; o[2] = pz[i]; o[3] = pw[i];
            float* o2 = cent_out2 + ((size_t)b * MM + m) * 4;
            o2[0] = px[i]; o2[1] = py[i]; o2[2] = pz[i]; o2[3] = pw[i];
        }
        __syncthreads();
        if (m == MM - 1) break;
        float lx = last[0], ly = last[1], lz = last[2], lw = last[3];
        // per-thread float argmax (strict > keeps FIRST/smallest p; p ascending in i)
        float bestv = -1.0f;
        int   besti = 0;
#pragma unroll
        for (int i = 0; i < 8; i++) {
            float dx = __fsub_rn(px[i], lx);
            float dy = __fsub_rn(py[i], ly);
            float dz = __fsub_rn(pz[i], lz);
            float dw = __fsub_rn(pw[i], lw);
            float d = __fadd_rn(__fadd_rn(__fadd_rn(__fmul_rn(dx,dx), __fmul_rn(dy,dy)),
                                          __fmul_rn(dz,dz)), __fmul_rn(dw,dw));
            float dm = fminf(dmin[i], d);
            dmin[i] = dm;
            if (dm > bestv) { bestv = dm; besti = tid + i * 1024; }
        }
        // pack once per thread; key max -> (max dmin, then min index)
        unsigned long long best = ((unsigned long long)__float_as_uint(bestv) << 32)
                                | (unsigned)(0x7FFFFFFF - besti);
        for (int off = 16; off; off >>= 1) {
            unsigned long long o = __shfl_down_sync(0xFFFFFFFFu, best, off);
            if (o > best) best = o;
        }
        if ((tid & 31) == 0) red[tid >> 5] = best;
        __syncthreads();
        if (tid < 32) {
            unsigned long long v = red[tid];
            for (int off = 16; off; off >>= 1) {
                unsigned long long o = __shfl_down_sync(0xFFFFFFFFu, v, off);
                if (o > v) v = o;
            }
            if (tid == 0) cur_s = 0x7FFFFFFF - (int)(v & 0xFFFFFFFFu);
        }
        __syncthreads();
        cur = cur_s;
    }
}

// ---------------- kNN: tournament selection (bit-exact picks) ----------------------
__global__ __launch_bounds__(256) void knn_kernel(const float* __restrict__ coords,
                                                  int* __restrict__ knn)
{
    extern __shared__ unsigned long long keys[];   // PP entries
    __shared__ unsigned long long red[8];
    __shared__ unsigned long long win_s;
    int m = blockIdx.x, b = blockIdx.y;
    int tid = threadIdx.x;
    const float* c = g_cent + ((size_t)b * MM + m) * 4;
    float c0 = c[0], c1 = c[1], c2 = c[2], c3 = c[3];
    float cen2 = __fadd_rn(__fadd_rn(__fadd_rn(__fmul_rn(c0,c0), __fmul_rn(c1,c1)),
                                     __fmul_rn(c2,c2)), __fmul_rn(c3,c3));
    unsigned long long mymin = ~0ull;
#pragma unroll 4
    for (int it = 0; it < PP / 256; it++) {
        int p = tid + it * 256;
        const float* q = coords + ((size_t)b * PP + p) * 5;
        float x0 = q[1], x1 = q[2], x2 = q[3], x3 = q[4];
        float pts2 = __fadd_rn(__fadd_rn(__fadd_rn(__fmul_rn(x0,x0), __fmul_rn(x1,x1)),
                                         __fmul_rn(x2,x2)), __fmul_rn(x3,x3));
        float dot  = __fadd_rn(__fadd_rn(__fadd_rn(__fmul_rn(c0,x0), __fmul_rn(c1,x1)),
                                         __fmul_rn(c2,x2)), __fmul_rn(c3,x3));
        float d2 = __fsub_rn(__fadd_rn(cen2, pts2), __fmul_rn(2.0f, dot));
        unsigned u = __float_as_uint(d2);
        u = (u & 0x80000000u) ? ~u : (u | 0x80000000u);   // order-preserving map
        unsigned long long key = ((unsigned long long)u << 32) | (unsigned)p;
        keys[p] = key;
        if (key < mymin) mymin = key;
    }
    int* outp = knn + ((size_t)b * MM + m) * KNN;
    for (int k = 0; k < KNN; k++) {
        unsigned long long v = mymin;
        for (int off = 16; off; off >>= 1) {
            unsigned long long o = __shfl_down_sync(0xFFFFFFFFu, v, off);
            if (o < v) v = o;
        }
        if ((tid & 31) == 0) red[tid >> 5] = v;
        __syncthreads();
        if (tid == 0) {
            unsigned long long w = red[0];
#pragma unroll
            for (int j = 1; j < 8; j++) if (red[j] < w) w = red[j];
            win_s = w;
            outp[k] = (int)(w & 0xFFFFFFFFu);
        }
        __syncthreads();
        if (mymin == win_s) {
            keys[(unsigned)(mymin & 0xFFFFFFFFu)] = ~0ull;
            unsigned long long nm = ~0ull;
#pragma unroll 4
            for (int it = 0; it < PP / 256; it++) {
                unsigned long long t = keys[tid + it * 256];
                if (t < nm) nm = t;
            }
            mymin = nm;
        }
    }
}

// ---------------- gather + layer1 (6 -> 256, relu): 8 rows per block, fp16 out ----
__global__ __launch_bounds__(256) void gather_mlp1(const float* __restrict__ feats,
                                                   const float* __restrict__ W1,
                                                   const float* __restrict__ b1)
{
    int j = threadIdx.x;
    int rowbase = blockIdx.x * 8;
    float w[6];
#pragma unroll
    for (int t = 0; t < 6; t++) w[t] = W1[t * 256 + j];
    float bb = b1[j];
    __shared__ float fs[8][6];
    if (j < 48) {
        int r = j / 6, cidx = j % 6;
        int row = rowbase + r;
        int bidx = row >> 11;                       // row / (MM*KNN)
        int idx = g_knn[row];
        fs[r][cidx] = feats[((size_t)bidx * PP + idx) * 6 + cidx];
    }
    __syncthreads();
#pragma unroll
    for (int r = 0; r < 8; r++) {
        float acc = bb;
#pragma unroll
        for (int t = 0; t < 6; t++) acc = fmaf(fs[r][t], w[t], acc);
        g_bufA[(size_t)(rowbase + r) * 256 + j] = __float2half_rn(fmaxf(acc, 0.f));
    }
}

// ---------------- weight transposes + mask fill in one kernel ----------------------
#define TN_W2  (256*512)
#define TN_W3  (512*768)
#define TN_W44 (768*768)
#define TE1 TN_W2
#define TE2 (TE1 + TN_W3)
#define TE3 (TE2 + TN_W44)
#define TE4 (TE3 + TN_W44)
#define TE5 (TE4 + TN_W44)
#define TE6 (TE5 + QQ)
__global__ __launch_bounds__(256) void transpose_all(
    const float* __restrict__ W2, const float* __restrict__ W3,
    const float* __restrict__ W4, const float* __restrict__ Wa1,
    const float* __restrict__ Wa2, __half* __restrict__ Wt,
    float* __restrict__ masks)
{
    int i = blockIdx.x * 256 + threadIdx.x;
    const float* W; __half* dst; int N, K, j;
    if (i < TE1)      { j = i;       W = W2;  dst = Wt + OFF_W2T;  K = 256; N = 512; }
    else if (i < TE2) { j = i - TE1; W = W3;  dst = Wt + OFF_W3T;  K = 512; N = 768; }
    else if (i < TE3) { j = i - TE2; W = W4;  dst = Wt + OFF_W4T;  K = 768; N = 768; }
    else if (i < TE4) { j = i - TE3; W = Wa1; dst = Wt + OFF_WA1T; K = 768; N = 768; }
    else if (i < TE5) { j = i - TE4; W = Wa2; dst = Wt + OFF_WA2T; K = 768; N = 768; }
    else if (i < TE6) { masks[i - TE5] = 1.0f; return; }
    else return;
    int k = j / N, n = j % N;
    dst[(size_t)n * K + k] = __float2half_rn(W[j]);
}

// ================= fp16 mma.sync m16n8k16 GEMM, persistent CTAs ====================
// C[Mr,N] = act(A[Mr,K] @ Bt[N,K]^T + bias)    (A, Bt fp16; accumulate fp32)
// CTA tile 128x128, K chunks of 64 halves, 3-stage cp.async pipeline.
// Persistent: grid = min(T, 296); each CTA loops tiles t += gridDim.x.
#define SPAD 36                      // smem row stride in 32-bit words (=72 halves)
#define STG_MAT (128 * SPAD * 4)     // 18432 B per matrix per stage
#define STG_BYTES (2 * STG_MAT)      // 36864 B per stage (A + B)
#define NSTAGE 3
#define GSMEM (NSTAGE * STG_BYTES)   // 110592 B

__device__ __forceinline__ void cp16(uint32_t saddr, const void* g) {
    asm volatile("cp.async.cg.shared.global [%0], [%1], 16;" :: "r"(saddr), "l"(g));
}

template<bool RELU, bool POOL, bool HALF_OUT>
__global__ __launch_bounds__(256, 2) void mma_gemm(
    const __half* __restrict__ A, const __half* __restrict__ Bt,
    const float* __restrict__ bias, void* __restrict__ Cv,
    int N, int K, int tilesN, int T)
{
    extern __shared__ char dsm[];
    uint32_t sbase = (uint32_t)__cvta_generic_to_shared(dsm);
    int tid = threadIdx.x, wid = tid >> 5, lane = tid & 31;
    int gid = lane >> 2, tig = lane & 3;
    int m_base = (wid & 3) * 32;
    int n_base = (wid >> 2) * 64;

    int srow[4], sq[4];
#pragma unroll
    for (int r = 0; r < 4; r++) {
        int id = tid + 256 * r;
        srow[r] = id >> 3;          // 0..127
        sq[r]   = id & 7;           // 16B unit within row
    }
    int NC = K >> 6;   // chunks of 64 halves

    for (int t = blockIdx.x; t < T; t += gridDim.x) {
        __syncthreads();   // all warps done reading smem stages of previous tile
        int bx = t % tilesN, by = t / tilesN;

        const __half* Ag = A  + (size_t)(by * 128) * K;
        const __half* Bg = Bt + (size_t)(bx * 128) * K;

        float acc[2][8][4];
#pragma unroll
        for (int mt = 0; mt < 2; mt++)
#pragma unroll
            for (int nt = 0; nt < 8; nt++)
#pragma unroll
                for (int j = 0; j < 4; j++) acc[mt][nt][j] = 0.f;

#pragma unroll
        for (int s = 0; s < 2; s++) {
            int kb = s << 6;
            uint32_t stb = sbase + s * STG_BYTES;
#pragma unroll
            for (int r = 0; r < 4; r++) {
                uint32_t doff = (uint32_t)(srow[r] * (SPAD * 4) + sq[r] * 16);
                cp16(stb + doff,           Ag + (size_t)srow[r] * K + kb + sq[r] * 8);
                cp16(stb + STG_MAT + doff, Bg + (size_t)srow[r] * K + kb + sq[r] * 8);
            }
            asm volatile("cp.async.commit_group;" ::: "memory");
        }

        for (int c = 0; c < NC; c++) {
            asm volatile("cp.async.wait_group 1;" ::: "memory");
            __syncthreads();

            if (c + 2 < NC) {
                int kb = (c + 2) << 6;
                uint32_t stb = sbase + ((c + 2) % NSTAGE) * STG_BYTES;
#pragma unroll
                for (int r = 0; r < 4; r++) {
                    uint32_t doff = (uint32_t)(srow[r] * (SPAD * 4) + sq[r] * 16);
                    cp16(stb + doff,           Ag + (size_t)srow[r] * K + kb + sq[r] * 8);
                    cp16(stb + STG_MAT + doff, Bg + (size_t)srow[r] * K + kb + sq[r] * 8);
                }
            }
            asm volatile("cp.async.commit_group;" ::: "memory");

            const uint32_t* As = (const uint32_t*)(dsm + (c % NSTAGE) * STG_BYTES);
            const uint32_t* Bs = As + 128 * SPAD;

#pragma unroll
            for (int ks = 0; ks < 4; ks++) {
                int k0 = ks * 8;
                uint32_t af[2][4];
#pragma unroll
                for (int mt = 0; mt < 2; mt++) {
                    int row = m_base + mt * 16 + gid;
                    af[mt][0] = As[row * SPAD + k0 + tig];
                    af[mt][1] = As[(row + 8) * SPAD + k0 + tig];
                    af[mt][2] = As[row * SPAD + k0 + tig + 4];
                    af[mt][3] = As[(row + 8) * SPAD + k0 + tig + 4];
                }
#pragma unroll
                for (int nt = 0; nt < 8; nt++) {
                    int col = n_base + nt * 8 + gid;
                    uint32_t b0 = Bs[col * SPAD + k0 + tig];
                    uint32_t b1 = Bs[col * SPAD + k0 + tig + 4];
#pragma unroll
                    for (int mt = 0; mt < 2; mt++) {
                        asm volatile(
                            "mma.sync.aligned.m16n8k16.row.col.f32.f16.f16.f32 "
                            "{%0,%1,%2,%3}, {%4,%5,%6,%7}, {%8,%9}, {%0,%1,%2,%3};"
                            : "+f"(acc[mt][nt][0]), "+f"(acc[mt][nt][1]),
                              "+f"(acc[mt][nt][2]), "+f"(acc[mt][nt][3])
                            : "r"(af[mt][0]), "r"(af[mt][1]), "r"(af[mt][2]), "r"(af[mt][3]),
                              "r"(b0), "r"(b1));
                    }
                }
            }
        }

        // ---- epilogue ----
#pragma unroll
        for (int nt = 0; nt < 8; nt++) {
            int cg = bx * 128 + n_base + nt * 8 + 2 * tig;
            float bz0 = bias[cg], bz1 = bias[cg + 1];
#pragma unroll
            for (int mt = 0; mt < 2; mt++) {
                float v0 = acc[mt][nt][0] + bz0;
                float v1 = acc[mt][nt][1] + bz1;
                float v2 = acc[mt][nt][2] + bz0;
                float v3 = acc[mt][nt][3] + bz1;
                if (RELU) {
                    v0 = fmaxf(v0, 0.f); v1 = fmaxf(v1, 0.f);
                    v2 = fmaxf(v2, 0.f); v3 = fmaxf(v3, 0.f);
                }
                if (POOL) {
                    float m0 = fmaxf(v0, v2);
                    float m1 = fmaxf(v1, v3);
#pragma unroll
                    for (int off = 4; off <= 16; off <<= 1) {
                        m0 = fmaxf(m0, __shfl_xor_sync(0xFFFFFFFFu, m0, off));
                        m1 = fmaxf(m1, __shfl_xor_sync(0xFFFFFFFFu, m1, off));
                    }
                    if (gid == 0) {
                        int q = (by * 128 + m_base + mt * 16) >> 4;
                        __half* C = (__half*)Cv;
                        *(__half2*)(C + (size_t)q * N + cg) = __floats2half2_rn(m0, m1);
                    }
                } else if (HALF_OUT) {
                    int rg = by * 128 + m_base + mt * 16 + gid;
                    __half* C = (__half*)Cv;
                    *(__half2*)(C + (size_t)rg * N + cg)       = __floats2half2_rn(v0, v1);
                    *(__half2*)(C + (size_t)(rg + 8) * N + cg) = __floats2half2_rn(v2, v3);
                } else {
                    int rg = by * 128 + m_base + mt * 16 + gid;
                    float* C = (float*)Cv;
                    *(float2*)(C + (size_t)rg * N + cg)       = make_float2(v0, v1);
                    *(float2*)(C + (size_t)(rg + 8) * N + cg) = make_float2(v2, v3);
                }
            }
        }
    }
}

// ---------------- launcher ---------------------------------------------------------
static inline int pgrid(int T) { return T < 296 ? T : 296; }

extern "C" void kernel_launch(void* const* d_in, const int* in_sizes, int n_in,
                              void* d_out, int out_size)
{
    const float* coords = (const float*)d_in[0];
    const float* feats  = (const float*)d_in[1];
    const float* W1 = (const float*)d_in[2];  const float* b1 = (const float*)d_in[3];
    const float* W2 = (const float*)d_in[4];  const float* b2 = (const float*)d_in[5];
    const float* W3 = (const float*)d_in[6];  const float* b3 = (const float*)d_in[7];
    const float* W4 = (const float*)d_in[8];  const float* b4 = (const float*)d_in[9];
    const float* Wa1 = (const float*)d_in[10]; const float* ba1 = (const float*)d_in[11];
    const float* Wa2 = (const float*)d_in[12]; const float* ba2 = (const float*)d_in[13];

    float* out     = (float*)d_out;
    float* tokens  = out;                               // [QQ, DD]
    float* centout = out + (size_t)QQ * DD;             // [QQ, 4]
    float* masks   = centout + (size_t)QQ * 4;          // [QQ]

    __half *pA, *pB, *pPool, *pH, *pWt;
    int* pKnn;
    cudaGetSymbolAddress((void**)&pA, g_bufA);
    cudaGetSymbolAddress((void**)&pB, g_bufB);
    cudaGetSymbolAddress((void**)&pPool, g_pool);
    cudaGetSymbolAddress((void**)&pH, g_h);
    cudaGetSymbolAddress((void**)&pKnn, g_knn);
    cudaGetSymbolAddress((void**)&pWt, g_wt);

    // 1. FPS -> centroids
    fps_kernel<<<BB, 1024>>>(coords, centout);

    // 2. weight transposes + mask fill (single kernel)
    transpose_all<<<(TE6 + 255) / 256, 256>>>(W2, W3, W4, Wa1, Wa2, pWt, masks);

    // 3. kNN (64KB dynamic smem, tournament selection)
    cudaFuncSetAttribute(knn_kernel, cudaFuncAttributeMaxDynamicSharedMemorySize, PP * 8);
    knn_kernel<<<dim3(MM, BB), 256, PP * 8>>>(coords, pKnn);

    // 4. gather + layer1 (6 -> 256, relu, fp16 out) -> g_bufA
    gather_mlp1<<<RR / 8, 256>>>(feats, W1, b1);

    // 5. MLP chain on fp16 tensor cores (persistent); layer 4 fuses the max-pool
    cudaFuncSetAttribute((const void*)mma_gemm<true,  false, true >, cudaFuncAttributeMaxDynamicSharedMemorySize, GSMEM);
    cudaFuncSetAttribute((const void*)mma_gemm<false, true,  true >, cudaFuncAttributeMaxDynamicSharedMemorySize, GSMEM);
    cudaFuncSetAttribute((const void*)mma_gemm<false, false, false>, cudaFuncAttributeMaxDynamicSharedMemorySize, GSMEM);
    {
        int tn, T;
        tn = 512 / 128; T = tn * (RR / 128);
        mma_gemm<true,  false, true ><<<pgrid(T), 256, GSMEM>>>(pA, pWt + OFF_W2T, b2, pB, 512, 256, tn, T);
        tn = 768 / 128; T = tn * (RR / 128);
        mma_gemm<true,  false, true ><<<pgrid(T), 256, GSMEM>>>(pB, pWt + OFF_W3T, b3, pA, 768, 512, tn, T);
        // layer 4: output pooled directly into g_pool [QQ, 768] (fp16)
        mma_gemm<false, true,  true ><<<pgrid(T), 256, GSMEM>>>(pA, pWt + OFF_W4T, b4, pPool, 768, 768, tn, T);

        // attention MLP -> tokens (final layer fp32 out)
        tn = DD / 128; T = tn * (QQ / 128);
        mma_gemm<true,  false, true ><<<pgrid(T), 256, GSMEM>>>(pPool, pWt + OFF_WA1T, ba1, pH, 768, 768, tn, T);
        mma_gemm<false, false, false><<<pgrid(T), 256, GSMEM>>>(pH, pWt + OFF_WA2T, ba2, tokens, 768, 768, tn, T);
    }
}

// round 13
// speedup vs baseline: 1.1538x; 1.1538x over previous
#include <cuda_runtime.h>
#include <cuda_fp16.h>
#include <stdint.h>

#define BB 16
#define PP 8192
#define MM 128
#define KNN 16
#define DD 768
#define QQ (BB*MM)      // 2048 queries/tokens
#define RR (QQ*KNN)     // 32768 gathered rows

// ---------------- scratch (device globals; no allocation allowed) ----------------
__device__ float  g_cent[QQ*4];
__device__ int    g_knn[RR];
__device__ int    g_prog[BB];
__device__ __half g_bufA[(size_t)RR*768];
__device__ __half g_bufB[(size_t)RR*768];
__device__ __half g_pool[(size_t)QQ*DD];
__device__ __half g_h[(size_t)QQ*DD];
// transposed weights [N][K] (K-major so B operand is k-contiguous = "col" for mma)
#define OFF_W2T  0
#define OFF_W3T  (512*256)
#define OFF_W4T  (OFF_W3T + 768*512)
#define OFF_WA1T (OFF_W4T + 768*768)
#define OFF_WA2T (OFF_WA1T + 768*768)
__device__ __half g_wt[OFF_WA2T + 768*768];

// transpose ranges (element counts)
#define TN_W2  (256*512)
#define TN_W3  (512*768)
#define TN_W44 (768*768)
#define TE1 TN_W2
#define TE2 (TE1 + TN_W3)
#define TE3 (TE2 + TN_W44)
#define TE4 (TE3 + TN_W44)
#define TE5 (TE4 + TN_W44)
#define TE6 (TE5 + QQ)
#define NT_BLK ((TE6 + 1023) / 1024)        // transpose blocks (1024 thr each)
#define FUSED_GRID (BB + NT_BLK + QQ)       // fps + transpose + knn blocks

// ---------------- reset progress flags (runs before fused kernel each replay) -----
__global__ void reset_prog()
{
    if (threadIdx.x < BB) g_prog[threadIdx.x] = 0;
}

// ================= fused FPS + transpose + kNN ====================================
// blocks [0,16):            FPS, one block per batch (bit-exact selection math)
// blocks [16,16+NT_BLK):    weight transpose (fp16) + mask fill
// blocks [16+NT_BLK, ...):  kNN, one block per (m,b); spins until centroid ready
__global__ __launch_bounds__(1024) void fused_front(
    const float* __restrict__ coords,
    float* __restrict__ cent_out2,
    const float* __restrict__ W2, const float* __restrict__ W3,
    const float* __restrict__ W4, const float* __restrict__ Wa1,
    const float* __restrict__ Wa2, float* __restrict__ masks)
{
    int bid = blockIdx.x;
    int tid = threadIdx.x;

    if (bid < BB) {
        // ---------------- FPS ----------------
        int b = bid;
        float px[8], py[8], pz[8], pw[8], dmin[8];
#pragma unroll
        for (int i = 0; i < 8; i++) {
            int p = tid + i * 1024;
            const float* c = coords + ((size_t)b * PP + p) * 5;
            px[i] = c[1]; py[i] = c[2]; pz[i] = c[3]; pw[i] = c[4];
            dmin[i] = 1e30f;
        }
        __shared__ float last[4];
        __shared__ unsigned long long red[32];
        __shared__ int cur_s;
        int cur = 0;
        for (int m = 0; m < MM; m++) {
            if (tid == (cur & 1023)) {
                int i = cur >> 10;
                last[0] = px[i]; last[1] = py[i]; last[2] = pz[i]; last[3] = pw[i];
                float* o  = g_cent + ((size_t)b * MM + m) * 4;
                o[0] = px[i]; o[1] = py[i]; o[2] = pz[i]; o[3] = pw[i];
                float* o2 = cent_out2 + ((size_t)b * MM + m) * 4;
                o2[0] = px[i]; o2[1] = py[i]; o2[2] = pz[i]; o2[3] = pw[i];
                __threadfence();
                ((volatile int*)g_prog)[b] = m + 1;      // release centroid m
            }
            __syncthreads();
            if (m == MM - 1) break;
            float lx = last[0], ly = last[1], lz = last[2], lw = last[3];
            float bestv = -1.0f;
            int   besti = 0;
#pragma unroll
            for (int i = 0; i < 8; i++) {
                float dx = __fsub_rn(px[i], lx);
                float dy = __fsub_rn(py[i], ly);
                float dz = __fsub_rn(pz[i], lz);
                float dw = __fsub_rn(pw[i], lw);
                float d = __fadd_rn(__fadd_rn(__fadd_rn(__fmul_rn(dx,dx), __fmul_rn(dy,dy)),
                                              __fmul_rn(dz,dz)), __fmul_rn(dw,dw));
                float dm = fminf(dmin[i], d);
                dmin[i] = dm;
                if (dm > bestv) { bestv = dm; besti = tid + i * 1024; }
            }
            unsigned long long best = ((unsigned long long)__float_as_uint(bestv) << 32)
                                    | (unsigned)(0x7FFFFFFF - besti);
            for (int off = 16; off; off >>= 1) {
                unsigned long long o = __shfl_down_sync(0xFFFFFFFFu, best, off);
                if (o > best) best = o;
            }
            if ((tid & 31) == 0) red[tid >> 5] = best;
            __syncthreads();
            if (tid < 32) {
                unsigned long long v = red[tid];
                for (int off = 16; off; off >>= 1) {
                    unsigned long long o = __shfl_down_sync(0xFFFFFFFFu, v, off);
                    if (o > v) v = o;
                }
                if (tid == 0) cur_s = 0x7FFFFFFF - (int)(v & 0xFFFFFFFFu);
            }
            __syncthreads();
            cur = cur_s;
        }
        return;
    }

    if (bid < BB + NT_BLK) {
        // ---------------- weight transpose + mask fill ----------------
        int i = (bid - BB) * 1024 + tid;
        const float* W; __half* dst; int N, K, j;
        if (i < TE1)      { j = i;       W = W2;  dst = g_wt + OFF_W2T;  K = 256; N = 512; }
        else if (i < TE2) { j = i - TE1; W = W3;  dst = g_wt + OFF_W3T;  K = 512; N = 768; }
        else if (i < TE3) { j = i - TE2; W = W4;  dst = g_wt + OFF_W4T;  K = 768; N = 768; }
        else if (i < TE4) { j = i - TE3; W = Wa1; dst = g_wt + OFF_WA1T; K = 768; N = 768; }
        else if (i < TE5) { j = i - TE4; W = Wa2; dst = g_wt + OFF_WA2T; K = 768; N = 768; }
        else if (i < TE6) { masks[i - TE5] = 1.0f; return; }
        else return;
        int k = j / N, n = j % N;
        dst[(size_t)n * K + k] = __float2half_rn(W[j]);
        return;
    }

    // ---------------- kNN (1024 threads, 8 pts/thread) ----------------
    {
        extern __shared__ unsigned long long keys[];   // PP entries
        __shared__ unsigned long long red2[32];
        __shared__ unsigned long long win_s;
        int lin = bid - BB - NT_BLK;
        int m = lin >> 4;          // slow: early blocks need early centroids
        int b = lin & 15;

        if (tid == 0) {
            while (((volatile int*)g_prog)[b] <= m) __nanosleep(100);
            __threadfence();       // acquire
        }
        __syncthreads();

        const float* c = g_cent + ((size_t)b * MM + m) * 4;
        float c0 = __ldcg(c + 0), c1 = __ldcg(c + 1), c2 = __ldcg(c + 2), c3 = __ldcg(c + 3);
        float cen2 = __fadd_rn(__fadd_rn(__fadd_rn(__fmul_rn(c0,c0), __fmul_rn(c1,c1)),
                                         __fmul_rn(c2,c2)), __fmul_rn(c3,c3));
        unsigned long long mymin = ~0ull;
#pragma unroll
        for (int it = 0; it < PP / 1024; it++) {
            int p = tid + it * 1024;
            const float* q = coords + ((size_t)b * PP + p) * 5;
            float x0 = q[1], x1 = q[2], x2 = q[3], x3 = q[4];
            float pts2 = __fadd_rn(__fadd_rn(__fadd_rn(__fmul_rn(x0,x0), __fmul_rn(x1,x1)),
                                             __fmul_rn(x2,x2)), __fmul_rn(x3,x3));
            float dot  = __fadd_rn(__fadd_rn(__fadd_rn(__fmul_rn(c0,x0), __fmul_rn(c1,x1)),
                                             __fmul_rn(c2,x2)), __fmul_rn(c3,x3));
            float d2 = __fsub_rn(__fadd_rn(cen2, pts2), __fmul_rn(2.0f, dot));
            unsigned u = __float_as_uint(d2);
            u = (u & 0x80000000u) ? ~u : (u | 0x80000000u);   // order-preserving map
            unsigned long long key = ((unsigned long long)u << 32) | (unsigned)p;
            keys[p] = key;
            if (key < mymin) mymin = key;
        }
        __syncthreads();   // (keys thread-private, but cheap safety for rescan path)

        int* outp = g_knn + ((size_t)b * MM + m) * KNN;
        for (int k = 0; k < KNN; k++) {
            unsigned long long v = mymin;
            for (int off = 16; off; off >>= 1) {
                unsigned long long o = __shfl_down_sync(0xFFFFFFFFu, v, off);
                if (o < v) v = o;
            }
            if ((tid & 31) == 0) red2[tid >> 5] = v;
            __syncthreads();
            if (tid < 32) {
                unsigned long long w = red2[tid];
                for (int off = 16; off; off >>= 1) {
                    unsigned long long o = __shfl_down_sync(0xFFFFFFFFu, w, off);
                    if (o < w) w = o;
                }
                if (tid == 0) {
                    win_s = w;
                    outp[k] = (int)(w & 0xFFFFFFFFu);
                }
            }
            __syncthreads();
            if (mymin == win_s) {          // unique winner (index embedded in key)
                keys[(unsigned)(mymin & 0xFFFFFFFFu)] = ~0ull;
                unsigned long long nm = ~0ull;
#pragma unroll
                for (int it = 0; it < PP / 1024; it++) {
                    unsigned long long t = keys[tid + it * 1024];
                    if (t < nm) nm = t;
                }
                mymin = nm;
            }
        }
    }
}

// ---------------- gather + layer1 (6 -> 256, relu): 8 rows per block, fp16 out ----
__global__ __launch_bounds__(256) void gather_mlp1(const float* __restrict__ feats,
                                                   const float* __restrict__ W1,
                                                   const float* __restrict__ b1)
{
    int j = threadIdx.x;
    int rowbase = blockIdx.x * 8;
    float w[6];
#pragma unroll
    for (int t = 0; t < 6; t++) w[t] = W1[t * 256 + j];
    float bb = b1[j];
    __shared__ float fs[8][6];
    if (j < 48) {
        int r = j / 6, cidx = j % 6;
        int row = rowbase + r;
        int bidx = row >> 11;                       // row / (MM*KNN)
        int idx = g_knn[row];
        fs[r][cidx] = feats[((size_t)bidx * PP + idx) * 6 + cidx];
    }
    __syncthreads();
#pragma unroll
    for (int r = 0; r < 8; r++) {
        float acc = bb;
#pragma unroll
        for (int t = 0; t < 6; t++) acc = fmaf(fs[r][t], w[t], acc);
        g_bufA[(size_t)(rowbase + r) * 256 + j] = __float2half_rn(fmaxf(acc, 0.f));
    }
}

// ================= fp16 mma.sync m16n8k16 GEMM, 3-stage cp.async pipeline ==========
// C[Mr,N] = act(A[Mr,K] @ Bt[N,K]^T + bias)    (A, Bt fp16; accumulate fp32)
// CTA tile 128x128, K chunks of 64 halves. 8 warps: 4(m)x2(n). Plain grid launch.
#define SPAD 36                      // smem row stride in 32-bit words (=72 halves)
#define STG_MAT (128 * SPAD * 4)     // 18432 B per matrix per stage
#define STG_BYTES (2 * STG_MAT)      // 36864 B per stage (A + B)
#define NSTAGE 3
#define GSMEM (NSTAGE * STG_BYTES)   // 110592 B

__device__ __forceinline__ void cp16(uint32_t saddr, const void* g) {
    asm volatile("cp.async.cg.shared.global [%0], [%1], 16;" :: "r"(saddr), "l"(g));
}

template<bool RELU, bool POOL, bool HALF_OUT>
__global__ __launch_bounds__(256, 2) void mma_gemm(
    const __half* __restrict__ A, const __half* __restrict__ Bt,
    const float* __restrict__ bias, void* __restrict__ Cv,
    int N, int K)
{
    extern __shared__ char dsm[];
    uint32_t sbase = (uint32_t)__cvta_generic_to_shared(dsm);
    int tid = threadIdx.x, wid = tid >> 5, lane = tid & 31;
    int gid = lane >> 2, tig = lane & 3;
    int bx = blockIdx.x, by = blockIdx.y;
    int m_base = (wid & 3) * 32;
    int n_base = (wid >> 2) * 64;

    const __half* Ag = A  + (size_t)(by * 128) * K;
    const __half* Bg = Bt + (size_t)(bx * 128) * K;

    int srow[4], sq[4];
#pragma unroll
    for (int r = 0; r < 4; r++) {
        int id = tid + 256 * r;
        srow[r] = id >> 3;          // 0..127
        sq[r]   = id & 7;           // 16B unit within row
    }

    float acc[2][8][4];
#pragma unroll
    for (int mt = 0; mt < 2; mt++)
#pragma unroll
        for (int nt = 0; nt < 8; nt++)
#pragma unroll
            for (int j = 0; j < 4; j++) acc[mt][nt][j] = 0.f;

    int NC = K >> 6;   // chunks of 64 halves

#pragma unroll
    for (int s = 0; s < 2; s++) {
        int kb = s << 6;
        uint32_t stb = sbase + s * STG_BYTES;
#pragma unroll
        for (int r = 0; r < 4; r++) {
            uint32_t doff = (uint32_t)(srow[r] * (SPAD * 4) + sq[r] * 16);
            cp16(stb + doff,           Ag + (size_t)srow[r] * K + kb + sq[r] * 8);
            cp16(stb + STG_MAT + doff, Bg + (size_t)srow[r] * K + kb + sq[r] * 8);
        }
        asm volatile("cp.async.commit_group;" ::: "memory");
    }

    for (int c = 0; c < NC; c++) {
        asm volatile("cp.async.wait_group 1;" ::: "memory");
        __syncthreads();

        if (c + 2 < NC) {
            int kb = (c + 2) << 6;
            uint32_t stb = sbase + ((c + 2) % NSTAGE) * STG_BYTES;
#pragma unroll
            for (int r = 0; r < 4; r++) {
                uint32_t doff = (uint32_t)(srow[r] * (SPAD * 4) + sq[r] * 16);
                cp16(stb + doff,           Ag + (size_t)srow[r] * K + kb + sq[r] * 8);
                cp16(stb + STG_MAT + doff, Bg + (size_t)srow[r] * K + kb + sq[r] * 8);
            }
        }
        asm volatile("cp.async.commit_group;" ::: "memory");

        const uint32_t* As = (const uint32_t*)(dsm + (c % NSTAGE) * STG_BYTES);
        const uint32_t* Bs = As + 128 * SPAD;

#pragma unroll
        for (int ks = 0; ks < 4; ks++) {
            int k0 = ks * 8;
            uint32_t af[2][4];
#pragma unroll
            for (int mt = 0; mt < 2; mt++) {
                int row = m_base + mt * 16 + gid;
                af[mt][0] = As[row * SPAD + k0 + tig];
                af[mt][1] = As[(row + 8) * SPAD + k0 + tig];
                af[mt][2] = As[row * SPAD + k0 + tig + 4];
                af[mt][3] = As[(row + 8) * SPAD + k0 + tig + 4];
            }
#pragma unroll
            for (int nt = 0; nt < 8; nt++) {
                int col = n_base + nt * 8 + gid;
                uint32_t b0 = Bs[col * SPAD + k0 + tig];
                uint32_t b1 = Bs[col * SPAD + k0 + tig + 4];
#pragma unroll
                for (int mt = 0; mt < 2; mt++) {
                    asm volatile(
                        "mma.sync.aligned.m16n8k16.row.col.f32.f16.f16.f32 "
                        "{%0,%1,%2,%3}, {%4,%5,%6,%7}, {%8,%9}, {%0,%1,%2,%3};"
                        : "+f"(acc[mt][nt][0]), "+f"(acc[mt][nt][1]),
                          "+f"(acc[mt][nt][2]), "+f"(acc[mt][nt][3])
                        : "r"(af[mt][0]), "r"(af[mt][1]), "r"(af[mt][2]), "r"(af[mt][3]),
                          "r"(b0), "r"(b1));
                }
            }
        }
    }

    // ---- epilogue ----
#pragma unroll
    for (int nt = 0; nt < 8; nt++) {
        int cg = bx * 128 + n_base + nt * 8 + 2 * tig;
        float bz0 = bias[cg], bz1 = bias[cg + 1];
#pragma unroll
        for (int mt = 0; mt < 2; mt++) {
            float v0 = acc[mt][nt][0] + bz0;
            float v1 = acc[mt][nt][1] + bz1;
            float v2 = acc[mt][nt][2] + bz0;
            float v3 = acc[mt][nt][3] + bz1;
            if (RELU) {
                v0 = fmaxf(v0, 0.f); v1 = fmaxf(v1, 0.f);
                v2 = fmaxf(v2, 0.f); v3 = fmaxf(v3, 0.f);
            }
            if (POOL) {
                float m0 = fmaxf(v0, v2);
                float m1 = fmaxf(v1, v3);
#pragma unroll
                for (int off = 4; off <= 16; off <<= 1) {
                    m0 = fmaxf(m0, __shfl_xor_sync(0xFFFFFFFFu, m0, off));
                    m1 = fmaxf(m1, __shfl_xor_sync(0xFFFFFFFFu, m1, off));
                }
                if (gid == 0) {
                    int q = (by * 128 + m_base + mt * 16) >> 4;
                    __half* C = (__half*)Cv;
                    *(__half2*)(C + (size_t)q * N + cg) = __floats2half2_rn(m0, m1);
                }
            } else if (HALF_OUT) {
                int rg = by * 128 + m_base + mt * 16 + gid;
                __half* C = (__half*)Cv;
                *(__half2*)(C + (size_t)rg * N + cg)       = __floats2half2_rn(v0, v1);
                *(__half2*)(C + (size_t)(rg + 8) * N + cg) = __floats2half2_rn(v2, v3);
            } else {
                int rg = by * 128 + m_base + mt * 16 + gid;
                float* C = (float*)Cv;
                *(float2*)(C + (size_t)rg * N + cg)       = make_float2(v0, v1);
                *(float2*)(C + (size_t)(rg + 8) * N + cg) = make_float2(v2, v3);
            }
        }
    }
}

// ---------------- launcher ---------------------------------------------------------
extern "C" void kernel_launch(void* const* d_in, const int* in_sizes, int n_in,
                              void* d_out, int out_size)
{
    const float* coords = (const float*)d_in[0];
    const float* feats  = (const float*)d_in[1];
    const float* W1 = (const float*)d_in[2];  const float* b1 = (const float*)d_in[3];
    const float* W2 = (const float*)d_in[4];  const float* b2 = (const float*)d_in[5];
    const float* W3 = (const float*)d_in[6];  const float* b3 = (const float*)d_in[7];
    const float* W4 = (const float*)d_in[8];  const float* b4 = (const float*)d_in[9];
    const float* Wa1 = (const float*)d_in[10]; const float* ba1 = (const float*)d_in[11];
    const float* Wa2 = (const float*)d_in[12]; const float* ba2 = (const float*)d_in[13];

    float* out     = (float*)d_out;
    float* tokens  = out;                               // [QQ, DD]
    float* centout = out + (size_t)QQ * DD;             // [QQ, 4]
    float* masks   = centout + (size_t)QQ * 4;          // [QQ]

    __half *pA, *pB, *pPool, *pH, *pWt;
    cudaGetSymbolAddress((void**)&pA, g_bufA);
    cudaGetSymbolAddress((void**)&pB, g_bufB);
    cudaGetSymbolAddress((void**)&pPool, g_pool);
    cudaGetSymbolAddress((void**)&pH, g_h);
    cudaGetSymbolAddress((void**)&pWt, g_wt);

    // 1. reset centroid-progress flags (must precede fused kernel every replay)
    reset_prog<<<1, 32>>>();

    // 2. fused FPS + transpose/mask + kNN (kNN overlaps FPS via progress flags)
    cudaFuncSetAttribute(fused_front, cudaFuncAttributeMaxDynamicSharedMemorySize, PP * 8);
    fused_front<<<FUSED_GRID, 1024, PP * 8>>>(coords, centout,
                                              W2, W3, W4, Wa1, Wa2, masks);

    // 3. gather + layer1 (6 -> 256, relu, fp16 out) -> g_bufA
    gather_mlp1<<<RR / 8, 256>>>(feats, W1, b1);

    // 4. MLP chain on fp16 tensor cores; layer 4 fuses the max-pool
    cudaFuncSetAttribute((const void*)mma_gemm<true,  false, true >, cudaFuncAttributeMaxDynamicSharedMemorySize, GSMEM);
    cudaFuncSetAttribute((const void*)mma_gemm<false, true,  true >, cudaFuncAttributeMaxDynamicSharedMemorySize, GSMEM);
    cudaFuncSetAttribute((const void*)mma_gemm<false, false, false>, cudaFuncAttributeMaxDynamicSharedMemorySize, GSMEM);
    mma_gemm<true,  false, true ><<<dim3(512 / 128, RR / 128), 256, GSMEM>>>(pA, pWt + OFF_W2T, b2, pB, 512, 256);
    mma_gemm<true,  false, true ><<<dim3(768 / 128, RR / 128), 256, GSMEM>>>(pB, pWt + OFF_W3T, b3, pA, 768, 512);
    // layer 4: output pooled directly into g_pool [QQ, 768] (fp16)
    mma_gemm<false, true,  true ><<<dim3(768 / 128, RR / 128), 256, GSMEM>>>(pA, pWt + OFF_W4T, b4, pPool, 768, 768);

    // 5. attention MLP -> tokens (final layer fp32 out)
    mma_gemm<true,  false, true ><<<dim3(DD / 128, QQ / 128), 256, GSMEM>>>(pPool, pWt + OFF_WA1T, ba1, pH, 768, 768);
    mma_gemm<false, false, false><<<dim3(DD / 128, QQ / 128), 256, GSMEM>>>(pH, pWt + OFF_WA2T, ba2, tokens, 768, 768);
}

// round 14
// speedup vs baseline: 1.1865x; 1.0283x over previous
#include <cuda_runtime.h>
#include <cuda_fp16.h>
#include <stdint.h>

#define BB 16
#define PP 8192
#define MM 128
#define KNN 16
#define DD 768
#define QQ (BB*MM)      // 2048 queries/tokens
#define RR (QQ*KNN)     // 32768 gathered rows

// ---------------- scratch (device globals; no allocation allowed) ----------------
__device__ float  g_cent[QQ*4];
__device__ int    g_knn[RR];
__device__ int    g_prog[BB];
__device__ __half g_bufA[(size_t)RR*768];
__device__ __half g_bufB[(size_t)RR*768];
__device__ __half g_pool[(size_t)QQ*DD];
__device__ __half g_h[(size_t)QQ*DD];
// transposed weights [N][K] (K-major so B operand is k-contiguous = "col" for mma)
#define OFF_W2T  0
#define OFF_W3T  (512*256)
#define OFF_W4T  (OFF_W3T + 768*512)
#define OFF_WA1T (OFF_W4T + 768*768)
#define OFF_WA2T (OFF_WA1T + 768*768)
__device__ __half g_wt[OFF_WA2T + 768*768];

// transpose ranges (element counts)
#define TN_W2  (256*512)
#define TN_W3  (512*768)
#define TN_W44 (768*768)
#define TE1 TN_W2
#define TE2 (TE1 + TN_W3)
#define TE3 (TE2 + TN_W44)
#define TE4 (TE3 + TN_W44)
#define TE5 (TE4 + TN_W44)
#define TE6 (TE5 + QQ)
#define NT_BLK ((TE6 + 1023) / 1024)        // transpose blocks (1024 thr each)
#define FUSED_GRID (BB + NT_BLK + QQ)       // fps + transpose + knn blocks

// ---------------- reset progress flags (runs before fused kernel each replay) -----
__global__ void reset_prog()
{
    if (threadIdx.x < BB) g_prog[threadIdx.x] = 0;
}

// ================= fused FPS + transpose + kNN ====================================
__global__ __launch_bounds__(1024) void fused_front(
    const float* __restrict__ coords,
    float* __restrict__ cent_out2,
    const float* __restrict__ W2, const float* __restrict__ W3,
    const float* __restrict__ W4, const float* __restrict__ Wa1,
    const float* __restrict__ Wa2, float* __restrict__ masks)
{
    int bid = blockIdx.x;
    int tid = threadIdx.x;

    if (bid < BB) {
        // ---------------- FPS ----------------
        int b = bid;
        float px[8], py[8], pz[8], pw[8], dmin[8];
#pragma unroll
        for (int i = 0; i < 8; i++) {
            int p = tid + i * 1024;
            const float* c = coords + ((size_t)b * PP + p) * 5;
            px[i] = c[1]; py[i] = c[2]; pz[i] = c[3]; pw[i] = c[4];
            dmin[i] = 1e30f;
        }
        __shared__ float last[4];
        __shared__ unsigned long long red[32];
        __shared__ int cur_s;
        int cur = 0;
        for (int m = 0; m < MM; m++) {
            if (tid == (cur & 1023)) {
                int i = cur >> 10;
                last[0] = px[i]; last[1] = py[i]; last[2] = pz[i]; last[3] = pw[i];
                float* o  = g_cent + ((size_t)b * MM + m) * 4;
                o[0] = px[i]; o[1] = py[i]; o[2] = pz[i]; o[3] = pw[i];
                float* o2 = cent_out2 + ((size_t)b * MM + m) * 4;
                o2[0] = px[i]; o2[1] = py[i]; o2[2] = pz[i]; o2[3] = pw[i];
                __threadfence();
                ((volatile int*)g_prog)[b] = m + 1;      // release centroid m
            }
            __syncthreads();
            if (m == MM - 1) break;
            float lx = last[0], ly = last[1], lz = last[2], lw = last[3];
            float bestv = -1.0f;
            int   besti = 0;
#pragma unroll
            for (int i = 0; i < 8; i++) {
                float dx = __fsub_rn(px[i], lx);
                float dy = __fsub_rn(py[i], ly);
                float dz = __fsub_rn(pz[i], lz);
                float dw = __fsub_rn(pw[i], lw);
                float d = __fadd_rn(__fadd_rn(__fadd_rn(__fmul_rn(dx,dx), __fmul_rn(dy,dy)),
                                              __fmul_rn(dz,dz)), __fmul_rn(dw,dw));
                float dm = fminf(dmin[i], d);
                dmin[i] = dm;
                if (dm > bestv) { bestv = dm; besti = tid + i * 1024; }
            }
            unsigned long long best = ((unsigned long long)__float_as_uint(bestv) << 32)
                                    | (unsigned)(0x7FFFFFFF - besti);
            for (int off = 16; off; off >>= 1) {
                unsigned long long o = __shfl_down_sync(0xFFFFFFFFu, best, off);
                if (o > best) best = o;
            }
            if ((tid & 31) == 0) red[tid >> 5] = best;
            __syncthreads();
            if (tid < 32) {
                unsigned long long v = red[tid];
                for (int off = 16; off; off >>= 1) {
                    unsigned long long o = __shfl_down_sync(0xFFFFFFFFu, v, off);
                    if (o > v) v = o;
                }
                if (tid == 0) cur_s = 0x7FFFFFFF - (int)(v & 0xFFFFFFFFu);
            }
            __syncthreads();
            cur = cur_s;
        }
        return;
    }

    if (bid < BB + NT_BLK) {
        // ---------------- weight transpose + mask fill ----------------
        int i = (bid - BB) * 1024 + tid;
        const float* W; __half* dst; int N, K, j;
        if (i < TE1)      { j = i;       W = W2;  dst = g_wt + OFF_W2T;  K = 256; N = 512; }
        else if (i < TE2) { j = i - TE1; W = W3;  dst = g_wt + OFF_W3T;  K = 512; N = 768; }
        else if (i < TE3) { j = i - TE2; W = W4;  dst = g_wt + OFF_W4T;  K = 768; N = 768; }
        else if (i < TE4) { j = i - TE3; W = Wa1; dst = g_wt + OFF_WA1T; K = 768; N = 768; }
        else if (i < TE5) { j = i - TE4; W = Wa2; dst = g_wt + OFF_WA2T; K = 768; N = 768; }
        else if (i < TE6) { masks[i - TE5] = 1.0f; return; }
        else return;
        int k = j / N, n = j % N;
        dst[(size_t)n * K + k] = __float2half_rn(W[j]);
        return;
    }

    // ---------------- kNN (1024 threads, 8 pts/thread) ----------------
    {
        extern __shared__ unsigned long long keys[];   // PP entries
        __shared__ unsigned long long red2[32];
        __shared__ unsigned long long win_s;
        int lin = bid - BB - NT_BLK;
        int m = lin >> 4;          // slow: early blocks need early centroids
        int b = lin & 15;

        if (tid == 0) {
            while (((volatile int*)g_prog)[b] <= m) __nanosleep(100);
            __threadfence();       // acquire
        }
        __syncthreads();

        const float* c = g_cent + ((size_t)b * MM + m) * 4;
        float c0 = __ldcg(c + 0), c1 = __ldcg(c + 1), c2 = __ldcg(c + 2), c3 = __ldcg(c + 3);
        float cen2 = __fadd_rn(__fadd_rn(__fadd_rn(__fmul_rn(c0,c0), __fmul_rn(c1,c1)),
                                         __fmul_rn(c2,c2)), __fmul_rn(c3,c3));
        unsigned long long mymin = ~0ull;
#pragma unroll
        for (int it = 0; it < PP / 1024; it++) {
            int p = tid + it * 1024;
            const float* q = coords + ((size_t)b * PP + p) * 5;
            float x0 = q[1], x1 = q[2], x2 = q[3], x3 = q[4];
            float pts2 = __fadd_rn(__fadd_rn(__fadd_rn(__fmul_rn(x0,x0), __fmul_rn(x1,x1)),
                                             __fmul_rn(x2,x2)), __fmul_rn(x3,x3));
            float dot  = __fadd_rn(__fadd_rn(__fadd_rn(__fmul_rn(c0,x0), __fmul_rn(c1,x1)),
                                             __fmul_rn(c2,x2)), __fmul_rn(c3,x3));
            float d2 = __fsub_rn(__fadd_rn(cen2, pts2), __fmul_rn(2.0f, dot));
            unsigned u = __float_as_uint(d2);
            u = (u & 0x80000000u) ? ~u : (u | 0x80000000u);   // order-preserving map
            unsigned long long key = ((unsigned long long)u << 32) | (unsigned)p;
            keys[p] = key;
            if (key < mymin) mymin = key;
        }
        __syncthreads();

        int* outp = g_knn + ((size_t)b * MM + m) * KNN;
        for (int k = 0; k < KNN; k++) {
            unsigned long long v = mymin;
            for (int off = 16; off; off >>= 1) {
                unsigned long long o = __shfl_down_sync(0xFFFFFFFFu, v, off);
                if (o < v) v = o;
            }
            if ((tid & 31) == 0) red2[tid >> 5] = v;
            __syncthreads();
            if (tid < 32) {
                unsigned long long w = red2[tid];
                for (int off = 16; off; off >>= 1) {
                    unsigned long long o = __shfl_down_sync(0xFFFFFFFFu, w, off);
                    if (o < w) w = o;
                }
                if (tid == 0) {
                    win_s = w;
                    outp[k] = (int)(w & 0xFFFFFFFFu);
                }
            }
            __syncthreads();
            if (mymin == win_s) {
                keys[(unsigned)(mymin & 0xFFFFFFFFu)] = ~0ull;
                unsigned long long nm = ~0ull;
#pragma unroll
                for (int it = 0; it < PP / 1024; it++) {
                    unsigned long long t = keys[tid + it * 1024];
                    if (t < nm) nm = t;
                }
                mymin = nm;
            }
        }
    }
}

// ---------------- gather + layer1 (6 -> 256, relu): 8 rows per block, fp16 out ----
__global__ __launch_bounds__(256) void gather_mlp1(const float* __restrict__ feats,
                                                   const float* __restrict__ W1,
                                                   const float* __restrict__ b1)
{
    int j = threadIdx.x;
    int rowbase = blockIdx.x * 8;
    float w[6];
#pragma unroll
    for (int t = 0; t < 6; t++) w[t] = W1[t * 256 + j];
    float bb = b1[j];
    __shared__ float fs[8][6];
    if (j < 48) {
        int r = j / 6, cidx = j % 6;
        int row = rowbase + r;
        int bidx = row >> 11;                       // row / (MM*KNN)
        int idx = g_knn[row];
        fs[r][cidx] = feats[((size_t)bidx * PP + idx) * 6 + cidx];
    }
    __syncthreads();
#pragma unroll
    for (int r = 0; r < 8; r++) {
        float acc = bb;
#pragma unroll
        for (int t = 0; t < 6; t++) acc = fmaf(fs[r][t], w[t], acc);
        g_bufA[(size_t)(rowbase + r) * 256 + j] = __float2half_rn(fmaxf(acc, 0.f));
    }
}

// ================= fp16 mma.sync m16n8k16 GEMM, ldmatrix fragment loads ============
// C[Mr,N] = act(A[Mr,K] @ Bt[N,K]^T + bias)    (A, Bt fp16; accumulate fp32)
// CTA tile 128x128, K chunks of 64 halves, 3-stage cp.async. 8 warps: 4(m)x2(n).
#define SPAD 36                      // smem row stride in 32-bit words (=72 halves)
#define STG_MAT (128 * SPAD * 4)     // 18432 B per matrix per stage
#define STG_BYTES (2 * STG_MAT)      // 36864 B per stage (A + B)
#define NSTAGE 3
#define GSMEM (NSTAGE * STG_BYTES)   // 110592 B

__device__ __forceinline__ void cp16(uint32_t saddr, const void* g) {
    asm volatile("cp.async.cg.shared.global [%0], [%1], 16;" :: "r"(saddr), "l"(g));
}
__device__ __forceinline__ void ldmx4(uint32_t& r0, uint32_t& r1, uint32_t& r2, uint32_t& r3,
                                      uint32_t saddr) {
    asm volatile("ldmatrix.sync.aligned.m8n8.x4.shared.b16 {%0,%1,%2,%3}, [%4];"
                 : "=r"(r0), "=r"(r1), "=r"(r2), "=r"(r3) : "r"(saddr));
}

template<bool RELU, bool POOL, bool HALF_OUT>
__global__ __launch_bounds__(256, 2) void mma_gemm(
    const __half* __restrict__ A, const __half* __restrict__ Bt,
    const float* __restrict__ bias, void* __restrict__ Cv,
    int N, int K)
{
    extern __shared__ char dsm[];
    uint32_t sbase = (uint32_t)__cvta_generic_to_shared(dsm);
    int tid = threadIdx.x, wid = tid >> 5, lane = tid & 31;
    int gid = lane >> 2, tig = lane & 3;
    int bx = blockIdx.x, by = blockIdx.y;
    int m_base = (wid & 3) * 32;
    int n_base = (wid >> 2) * 64;

    const __half* Ag = A  + (size_t)(by * 128) * K;
    const __half* Bg = Bt + (size_t)(bx * 128) * K;

    int srow[4], sq[4];
#pragma unroll
    for (int r = 0; r < 4; r++) {
        int id = tid + 256 * r;
        srow[r] = id >> 3;          // 0..127
        sq[r]   = id & 7;           // 16B unit within row
    }

    // ldmatrix per-thread word offsets (within a stage's A or B region)
    // A x4 (per mt): regs = {rows lo,k lo},{rows hi,k lo},{rows lo,k hi},{rows hi,k hi}
    // B x4 (per nt-pair): regs = {nt0,k lo},{nt0,k hi},{nt1,k lo},{nt1,k hi}
    int lr = lane & 7, mi = lane >> 3;
    int a_off[2], b_off[4];
#pragma unroll
    for (int mt = 0; mt < 2; mt++)
        a_off[mt] = (m_base + mt * 16 + lr + (mi & 1) * 8) * SPAD + (mi >> 1) * 4;
#pragma unroll
    for (int nt2 = 0; nt2 < 4; nt2++)
        b_off[nt2] = (n_base + nt2 * 16 + lr + (mi >> 1) * 8) * SPAD + (mi & 1) * 4;

    float acc[2][8][4];
#pragma unroll
    for (int mt = 0; mt < 2; mt++)
#pragma unroll
        for (int nt = 0; nt < 8; nt++)
#pragma unroll
            for (int j = 0; j < 4; j++) acc[mt][nt][j] = 0.f;

    int NC = K >> 6;   // chunks of 64 halves

#pragma unroll
    for (int s = 0; s < 2; s++) {
        int kb = s << 6;
        uint32_t stb = sbase + s * STG_BYTES;
#pragma unroll
        for (int r = 0; r < 4; r++) {
            uint32_t doff = (uint32_t)(srow[r] * (SPAD * 4) + sq[r] * 16);
            cp16(stb + doff,           Ag + (size_t)srow[r] * K + kb + sq[r] * 8);
            cp16(stb + STG_MAT + doff, Bg + (size_t)srow[r] * K + kb + sq[r] * 8);
        }
        asm volatile("cp.async.commit_group;" ::: "memory");
    }

    for (int c = 0; c < NC; c++) {
        asm volatile("cp.async.wait_group 1;" ::: "memory");
        __syncthreads();

        if (c + 2 < NC) {
            int kb = (c + 2) << 6;
            uint32_t stb = sbase + ((c + 2) % NSTAGE) * STG_BYTES;
#pragma unroll
            for (int r = 0; r < 4; r++) {
                uint32_t doff = (uint32_t)(srow[r] * (SPAD * 4) + sq[r] * 16);
                cp16(stb + doff,           Ag + (size_t)srow[r] * K + kb + sq[r] * 8);
                cp16(stb + STG_MAT + doff, Bg + (size_t)srow[r] * K + kb + sq[r] * 8);
            }
        }
        asm volatile("cp.async.commit_group;" ::: "memory");

        uint32_t aBase = sbase + (c % NSTAGE) * STG_BYTES;
        uint32_t bBase = aBase + STG_MAT;

#pragma unroll
        for (int ks = 0; ks < 4; ks++) {
            int k0 = ks * 8;
            uint32_t af[2][4];
#pragma unroll
            for (int mt = 0; mt < 2; mt++)
                ldmx4(af[mt][0], af[mt][1], af[mt][2], af[mt][3],
                      aBase + (uint32_t)(a_off[mt] + k0) * 4);
#pragma unroll
            for (int nt2 = 0; nt2 < 4; nt2++) {
                uint32_t bf0, bf1, bf2, bf3;
                ldmx4(bf0, bf1, bf2, bf3, bBase + (uint32_t)(b_off[nt2] + k0) * 4);
#pragma unroll
                for (int mt = 0; mt < 2; mt++) {
                    asm volatile(
                        "mma.sync.aligned.m16n8k16.row.col.f32.f16.f16.f32 "
                        "{%0,%1,%2,%3}, {%4,%5,%6,%7}, {%8,%9}, {%0,%1,%2,%3};"
                        : "+f"(acc[mt][nt2*2][0]), "+f"(acc[mt][nt2*2][1]),
                          "+f"(acc[mt][nt2*2][2]), "+f"(acc[mt][nt2*2][3])
                        : "r"(af[mt][0]), "r"(af[mt][1]), "r"(af[mt][2]), "r"(af[mt][3]),
                          "r"(bf0), "r"(bf1));
                }
#pragma unroll
                for (int mt = 0; mt < 2; mt++) {
                    asm volatile(
                        "mma.sync.aligned.m16n8k16.row.col.f32.f16.f16.f32 "
                        "{%0,%1,%2,%3}, {%4,%5,%6,%7}, {%8,%9}, {%0,%1,%2,%3};"
                        : "+f"(acc[mt][nt2*2+1][0]), "+f"(acc[mt][nt2*2+1][1]),
                          "+f"(acc[mt][nt2*2+1][2]), "+f"(acc[mt][nt2*2+1][3])
                        : "r"(af[mt][0]), "r"(af[mt][1]), "r"(af[mt][2]), "r"(af[mt][3]),
                          "r"(bf2), "r"(bf3));
                }
            }
        }
    }

    // ---- epilogue (fragment ownership identical to scalar-LDS version) ----
#pragma unroll
    for (int nt = 0; nt < 8; nt++) {
        int cg = bx * 128 + n_base + nt * 8 + 2 * tig;
        float bz0 = bias[cg], bz1 = bias[cg + 1];
#pragma unroll
        for (int mt = 0; mt < 2; mt++) {
            float v0 = acc[mt][nt][0] + bz0;
            float v1 = acc[mt][nt][1] + bz1;
            float v2 = acc[mt][nt][2] + bz0;
            float v3 = acc[mt][nt][3] + bz1;
            if (RELU) {
                v0 = fmaxf(v0, 0.f); v1 = fmaxf(v1, 0.f);
                v2 = fmaxf(v2, 0.f); v3 = fmaxf(v3, 0.f);
            }
            if (POOL) {
                float m0 = fmaxf(v0, v2);
                float m1 = fmaxf(v1, v3);
#pragma unroll
                for (int off = 4; off <= 16; off <<= 1) {
                    m0 = fmaxf(m0, __shfl_xor_sync(0xFFFFFFFFu, m0, off));
                    m1 = fmaxf(m1, __shfl_xor_sync(0xFFFFFFFFu, m1, off));
                }
                if (gid == 0) {
                    int q = (by * 128 + m_base + mt * 16) >> 4;
                    __half* C = (__half*)Cv;
                    *(__half2*)(C + (size_t)q * N + cg) = __floats2half2_rn(m0, m1);
                }
            } else if (HALF_OUT) {
                int rg = by * 128 + m_base + mt * 16 + gid;
                __half* C = (__half*)Cv;
                *(__half2*)(C + (size_t)rg * N + cg)       = __floats2half2_rn(v0, v1);
                *(__half2*)(C + (size_t)(rg + 8) * N + cg) = __floats2half2_rn(v2, v3);
            } else {
                int rg = by * 128 + m_base + mt * 16 + gid;
                float* C = (float*)Cv;
                *(float2*)(C + (size_t)rg * N + cg)       = make_float2(v0, v1);
                *(float2*)(C + (size_t)(rg + 8) * N + cg) = make_float2(v2, v3);
            }
        }
    }
}

// ---------------- launcher ---------------------------------------------------------
extern "C" void kernel_launch(void* const* d_in, const int* in_sizes, int n_in,
                              void* d_out, int out_size)
{
    const float* coords = (const float*)d_in[0];
    const float* feats  = (const float*)d_in[1];
    const float* W1 = (const float*)d_in[2];  const float* b1 = (const float*)d_in[3];
    const float* W2 = (const float*)d_in[4];  const float* b2 = (const float*)d_in[5];
    const float* W3 = (const float*)d_in[6];  const float* b3 = (const float*)d_in[7];
    const float* W4 = (const float*)d_in[8];  const float* b4 = (const float*)d_in[9];
    const float* Wa1 = (const float*)d_in[10]; const float* ba1 = (const float*)d_in[11];
    const float* Wa2 = (const float*)d_in[12]; const float* ba2 = (const float*)d_in[13];

    float* out     = (float*)d_out;
    float* tokens  = out;                               // [QQ, DD]
    float* centout = out + (size_t)QQ * DD;             // [QQ, 4]
    float* masks   = centout + (size_t)QQ * 4;          // [QQ]

    __half *pA, *pB, *pPool, *pH, *pWt;
    cudaGetSymbolAddress((void**)&pA, g_bufA);
    cudaGetSymbolAddress((void**)&pB, g_bufB);
    cudaGetSymbolAddress((void**)&pPool, g_pool);
    cudaGetSymbolAddress((void**)&pH, g_h);
    cudaGetSymbolAddress((void**)&pWt, g_wt);

    // 1. reset centroid-progress flags (must precede fused kernel every replay)
    reset_prog<<<1, 32>>>();

    // 2. fused FPS + transpose/mask + kNN (kNN overlaps FPS via progress flags)
    cudaFuncSetAttribute(fused_front, cudaFuncAttributeMaxDynamicSharedMemorySize, PP * 8);
    fused_front<<<FUSED_GRID, 1024, PP * 8>>>(coords, centout,
                                              W2, W3, W4, Wa1, Wa2, masks);

    // 3. gather + layer1 (6 -> 256, relu, fp16 out) -> g_bufA
    gather_mlp1<<<RR / 8, 256>>>(feats, W1, b1);

    // 4. MLP chain on fp16 tensor cores; layer 4 fuses the max-pool
    cudaFuncSetAttribute((const void*)mma_gemm<true,  false, true >, cudaFuncAttributeMaxDynamicSharedMemorySize, GSMEM);
    cudaFuncSetAttribute((const void*)mma_gemm<false, true,  true >, cudaFuncAttributeMaxDynamicSharedMemorySize, GSMEM);
    cudaFuncSetAttribute((const void*)mma_gemm<false, false, false>, cudaFuncAttributeMaxDynamicSharedMemorySize, GSMEM);
    mma_gemm<true,  false, true ><<<dim3(512 / 128, RR / 128), 256, GSMEM>>>(pA, pWt + OFF_W2T, b2, pB, 512, 256);
    mma_gemm<true,  false, true ><<<dim3(768 / 128, RR / 128), 256, GSMEM>>>(pB, pWt + OFF_W3T, b3, pA, 768, 512);
    // layer 4: output pooled directly into g_pool [QQ, 768] (fp16)
    mma_gemm<false, true,  true ><<<dim3(768 / 128, RR / 128), 256, GSMEM>>>(pA, pWt + OFF_W4T, b4, pPool, 768, 768);

    // 5. attention MLP -> tokens (final layer fp32 out)
    mma_gemm<true,  false, true ><<<dim3(DD / 128, QQ / 128), 256, GSMEM>>>(pPool, pWt + OFF_WA1T, ba1, pH, 768, 768);
    mma_gemm<false, false, false><<<dim3(DD / 128, QQ / 128), 256, GSMEM>>>(pH, pWt + OFF_WA2T, ba2, tokens, 768, 768);
}